// round 2
// baseline (speedup 1.0000x reference)
#include <cuda_runtime.h>
#include <math.h>

#define BSZ 8
#define LQ 8192
#define NTOK (BSZ*LQ)
#define NC 64
#define CL 128

// ---------------- scratch (device globals; no allocations allowed) ----------
__device__ float g_at[NTOK*128];
__device__ float g_bt[NTOK*128];
__device__ float g_hf[NTOK*128];
__device__ float g_hb[NTOK*128];
__device__ float g_cfA[BSZ*NC*128], g_cfB[BSZ*NC*128];
__device__ float g_cbA[BSZ*NC*128], g_cbB[BSZ*NC*128];
__device__ float g_carF[BSZ*NC*128], g_carB[BSZ*NC*128];
__device__ float g_scal[BSZ*6];   // s1,t1,g1,s2,t2,g2 per batch

__device__ __forceinline__ float warp_allred(float v){
#pragma unroll
    for (int o=16;o>0;o>>=1) v += __shfl_xor_sync(0xffffffffu, v, o);
    return v;
}

__device__ __forceinline__ float sigmoidf_(float z){
    return 1.f/(1.f+__expf(-z));
}

__device__ __forceinline__ float gelu_tanh(float v){
    // jax.nn.gelu approximate=True
    float t = tanhf(0.7978845608028654f * fmaf(0.044715f*v, v*v, v));
    return 0.5f*v*(1.f+t);
}

// ---------------- K0: conditioning scalars --------------------------------
__global__ __launch_bounds__(256) void k_affine(
    const float* __restrict__ c,
    const float* __restrict__ sw1, const float* __restrict__ sb1,
    const float* __restrict__ bw1, const float* __restrict__ bb1,
    const float* __restrict__ gw1, const float* __restrict__ gb1,
    const float* __restrict__ sw2, const float* __restrict__ sb2,
    const float* __restrict__ bw2, const float* __restrict__ bb2,
    const float* __restrict__ gw2, const float* __restrict__ gb2)
{
    int warp = threadIdx.x>>5, lane = threadIdx.x&31;
    if (warp >= BSZ) return;
    const float* ws[6] = {sw1,bw1,gw1,sw2,bw2,gw2};
    const float* bs[6] = {sb1,bb1,gb1,sb2,bb2,gb2};
    for (int j=0;j<6;j++){
        float s = 0.f;
        for (int i=lane;i<128;i+=32) s += c[warp*128+i]*ws[j][i];
#pragma unroll
        for (int o=16;o>0;o>>=1) s += __shfl_down_sync(0xffffffffu, s, o);
        if (lane==0) g_scal[warp*6+j] = s + bs[j][0];
    }
}

// --------------- 128x128x128 SGEMM tile helper (256 thr, 8x8 micro) --------
// sA: [128][132] resident A. gB: global B [128][128]. sW: [32][132] stream buf.
__device__ __forceinline__ void gemm128x128(
    const float* __restrict__ sA, const float* __restrict__ gB,
    float* __restrict__ sW, float acc[8][8], int tx, int ty)
{
    for (int kc=0;kc<4;kc++){
        __syncthreads();
        for (int i=threadIdx.x;i<1024;i+=256){
            int k = i>>5, n4 = i&31;
            *(float4*)(sW + k*132 + (n4<<2)) =
                *(const float4*)(gB + (size_t)((kc<<5)+k)*128 + (n4<<2));
        }
        __syncthreads();
#pragma unroll
        for (int kk=0;kk<32;kk++){
            float a8[8];
#pragma unroll
            for (int i=0;i<8;i++) a8[i] = sA[(ty*8+i)*132 + (kc<<5)+kk];
            float4 b0 = *(const float4*)(sW + kk*132 + tx*8);
            float4 b1 = *(const float4*)(sW + kk*132 + tx*8 + 4);
            float b8[8] = {b0.x,b0.y,b0.z,b0.w,b1.x,b1.y,b1.z,b1.w};
#pragma unroll
            for (int i=0;i<8;i++){
#pragma unroll
                for (int j=0;j<8;j++) acc[i][j] = fmaf(a8[i], b8[j], acc[i][j]);
            }
        }
    }
}

// ---------------- K1: LN chain + u/gi/gr GEMMs + at,bt ---------------------
__global__ __launch_bounds__(256) void k1_gates(
    const float* __restrict__ x,
    const float* __restrict__ Win, const float* __restrict__ bin,
    const float* __restrict__ pos,
    const float* __restrict__ Wi,  const float* __restrict__ bi,
    const float* __restrict__ Wr,  const float* __restrict__ br,
    const float* __restrict__ ra)
{
    extern __shared__ float sm[];
    float* sV = sm;                 // 128*132 : v = ln(h), later gi
    float* sU = sm + 128*132;       // 128*132 : u
    float* sW = sm + 2*128*132;     // 32*132  : weight stream
    const int t0 = blockIdx.x*128;
    const int b  = t0 / LQ;
    const int l0 = t0 % LQ;
    const float alpha = 1.f + g_scal[b*6+0];
    const float beta  = g_scal[b*6+1];
    const int warp = threadIdx.x>>5, lane = threadIdx.x&31;

    // LN(x) -> h -> LN(h) into sV  (warp per row)
    for (int r = warp; r < 128; r += 8){
        const float* xr = x + (size_t)(t0+r)*128;
        float v[4];
#pragma unroll
        for (int i=0;i<4;i++) v[i] = xr[lane+32*i];
        float m = warp_allred(v[0]+v[1]+v[2]+v[3]) * (1.f/128.f);
        float sq = 0.f;
#pragma unroll
        for (int i=0;i<4;i++){ v[i] -= m; sq += v[i]*v[i]; }
        float rs = rsqrtf(warp_allred(sq)*(1.f/128.f) + 1e-6f);
#pragma unroll
        for (int i=0;i<4;i++) v[i] = fmaf(alpha, v[i]*rs, beta);
        float m2 = warp_allred(v[0]+v[1]+v[2]+v[3]) * (1.f/128.f);
        float sq2 = 0.f;
#pragma unroll
        for (int i=0;i<4;i++){ v[i] -= m2; sq2 += v[i]*v[i]; }
        float rs2 = rsqrtf(warp_allred(sq2)*(1.f/128.f) + 1e-6f);
#pragma unroll
        for (int i=0;i<4;i++) sV[r*132 + lane+32*i] = v[i]*rs2;
    }

    const int tx = threadIdx.x & 15, ty = threadIdx.x >> 4;
    float acc[8][8];

    // u = v @ Win + bin + pos
#pragma unroll
    for (int i=0;i<8;i++){
#pragma unroll
        for (int j=0;j<8;j++) acc[i][j] = 0.f;
    }
    gemm128x128(sV, Win, sW, acc, tx, ty);
#pragma unroll
    for (int i=0;i<8;i++){
        int row = ty*8+i;
#pragma unroll
        for (int j=0;j<8;j++){
            int col = tx*8+j;
            sU[row*132+col] = acc[i][j] + bin[col] + pos[(size_t)(l0+row)*128 + col];
        }
    }

    // gi = sigmoid(u @ Wi + bi)  -> stored into sV
#pragma unroll
    for (int i=0;i<8;i++){
#pragma unroll
        for (int j=0;j<8;j++) acc[i][j] = 0.f;
    }
    gemm128x128(sU, Wi, sW, acc, tx, ty);
#pragma unroll
    for (int i=0;i<8;i++){
        int row = ty*8+i;
#pragma unroll
        for (int j=0;j<8;j++){
            int col = tx*8+j;
            sV[row*132+col] = sigmoidf_(acc[i][j] + bi[col]);
        }
    }

    // gr = sigmoid(u @ Wr + br); at, bt
#pragma unroll
    for (int i=0;i<8;i++){
#pragma unroll
        for (int j=0;j<8;j++) acc[i][j] = 0.f;
    }
    gemm128x128(sU, Wr, sW, acc, tx, ty);

    float la[8];
#pragma unroll
    for (int j=0;j<8;j++) la[j] = logf(ra[tx*8+j]);
#pragma unroll
    for (int i=0;i<8;i++){
        int row = ty*8+i;
#pragma unroll
        for (int j=0;j<8;j++){
            int col = tx*8+j;
            float grv = sigmoidf_(acc[i][j] + br[col]);
            float at  = expf(8.f*grv*la[j]);           // a^(c*r)
            float giv = sV[row*132+col];
            float uv  = sU[row*132+col];
            float btv = sqrtf(fmaxf(1.f - at*at, 0.f)) * giv * uv;
            size_t o  = (size_t)(t0+row)*128 + col;
            g_at[o] = at; g_bt[o] = btv;
        }
    }
}

// ---------------- K2: chunked bidirectional scan ---------------------------
__global__ __launch_bounds__(128) void k2_reduce(){
    int b = blockIdx.x, c = blockIdx.y, d = threadIdx.x;
    size_t base = ((size_t)b*LQ + (size_t)c*CL)*128 + d;
    const float* A = g_at + base;
    const float* B = g_bt + base;
    float Af=1.f, Bf=0.f;
#pragma unroll 4
    for (int i=0;i<CL;i++){ float a=A[(size_t)i*128], bb=B[(size_t)i*128]; Bf=fmaf(a,Bf,bb); Af*=a; }
    int ci = (b*NC+c)*128+d;
    g_cfA[ci]=Af; g_cfB[ci]=Bf;
    float Ab=1.f, Bb=0.f;
#pragma unroll 4
    for (int i=CL-1;i>=0;i--){ float a=A[(size_t)i*128], bb=B[(size_t)i*128]; Bb=fmaf(a,Bb,bb); Ab*=a; }
    g_cbA[ci]=Ab; g_cbB[ci]=Bb;
}

__global__ __launch_bounds__(128) void k2_carry(){
    int b = blockIdx.x, d = threadIdx.x;
    float h = 0.f;
    for (int c=0;c<NC;c++){
        int ci=(b*NC+c)*128+d;
        g_carF[ci]=h; h = fmaf(g_cfA[ci], h, g_cfB[ci]);
    }
    float h2 = 0.f;
    for (int c=NC-1;c>=0;c--){
        int ci=(b*NC+c)*128+d;
        g_carB[ci]=h2; h2 = fmaf(g_cbA[ci], h2, g_cbB[ci]);
    }
}

__global__ __launch_bounds__(128) void k2_apply(){
    int b = blockIdx.x, c = blockIdx.y, d = threadIdx.x;
    size_t base = ((size_t)b*LQ + (size_t)c*CL)*128 + d;
    int ci = (b*NC+c)*128+d;
    float h = g_carF[ci];
#pragma unroll 4
    for (int i=0;i<CL;i++){
        size_t o = base + (size_t)i*128;
        h = fmaf(g_at[o], h, g_bt[o]); g_hf[o] = h;
    }
    float h2 = g_carB[ci];
#pragma unroll 4
    for (int i=CL-1;i>=0;i--){
        size_t o = base + (size_t)i*128;
        h2 = fmaf(g_at[o], h2, g_bt[o]); g_hb[o] = h2;
    }
}

// ---------------- K3: r = [hf|hb]@Wo + bo; x2 = x + g1*r -> d_out ----------
__global__ __launch_bounds__(256) void k3_out(
    const float* __restrict__ x, const float* __restrict__ Wo,
    const float* __restrict__ bo, float* __restrict__ out)
{
    __shared__ float sA[128*36];
    __shared__ float sB[32*132];
    const int t0 = blockIdx.x*128;
    const int b  = t0 / LQ;
    const float g1 = g_scal[b*6+2];
    const int tx = threadIdx.x & 15, ty = threadIdx.x >> 4;
    float acc[8][8];
#pragma unroll
    for (int i=0;i<8;i++){
#pragma unroll
        for (int j=0;j<8;j++) acc[i][j] = 0.f;
    }
    for (int kc=0;kc<8;kc++){
        __syncthreads();
        for (int i=threadIdx.x;i<1024;i+=256){
            int m = i>>3, c4 = i&7;
            const float* src = (kc<4)
                ? (g_hf + (size_t)(t0+m)*128 + (kc<<5) + (c4<<2))
                : (g_hb + (size_t)(t0+m)*128 + ((kc-4)<<5) + (c4<<2));
            *(float4*)(sA + m*36 + (c4<<2)) = *(const float4*)src;
        }
        for (int i=threadIdx.x;i<1024;i+=256){
            int k = i>>5, n4 = i&31;
            *(float4*)(sB + k*132 + (n4<<2)) =
                *(const float4*)(Wo + (size_t)((kc<<5)+k)*128 + (n4<<2));
        }
        __syncthreads();
#pragma unroll
        for (int kk=0;kk<32;kk++){
            float a8[8];
#pragma unroll
            for (int i=0;i<8;i++) a8[i] = sA[(ty*8+i)*36 + kk];
            float4 b0 = *(const float4*)(sB + kk*132 + tx*8);
            float4 b1 = *(const float4*)(sB + kk*132 + tx*8 + 4);
            float b8[8] = {b0.x,b0.y,b0.z,b0.w,b1.x,b1.y,b1.z,b1.w};
#pragma unroll
            for (int i=0;i<8;i++){
#pragma unroll
                for (int j=0;j<8;j++) acc[i][j] = fmaf(a8[i], b8[j], acc[i][j]);
            }
        }
    }
#pragma unroll
    for (int i=0;i<8;i++){
        int row = ty*8+i;
#pragma unroll
        for (int j=0;j<8;j++){
            int col = tx*8+j;
            size_t o = (size_t)(t0+row)*128 + col;
            out[o] = fmaf(g1, acc[i][j] + bo[col], x[o]);
        }
    }
}

// ---------------- K4: conditioned LN + gelu MLP + gated residual (in place)-
__global__ __launch_bounds__(256) void k4_mlp(
    float* __restrict__ xo,
    const float* __restrict__ W1, const float* __restrict__ b1,
    const float* __restrict__ W2, const float* __restrict__ b2)
{
    extern __shared__ float sm[];
    float* sH = sm;               // 64*132
    float* sM = sm + 64*132;      // 64*132
    float* sW = sm + 2*64*132;    // 32*132
    const int t0 = blockIdx.x*64;
    const int b  = t0 / LQ;
    const float alpha = 1.f + g_scal[b*6+3];
    const float beta  = g_scal[b*6+4];
    const float g2    = g_scal[b*6+5];
    const int warp = threadIdx.x>>5, lane = threadIdx.x&31;

    for (int r = warp; r < 64; r += 8){
        const float* xr = xo + (size_t)(t0+r)*128;
        float v[4];
#pragma unroll
        for (int i=0;i<4;i++) v[i] = xr[lane+32*i];
        float m = warp_allred(v[0]+v[1]+v[2]+v[3]) * (1.f/128.f);
        float sq = 0.f;
#pragma unroll
        for (int i=0;i<4;i++){ v[i] -= m; sq += v[i]*v[i]; }
        float rs = rsqrtf(warp_allred(sq)*(1.f/128.f) + 1e-6f);
#pragma unroll
        for (int i=0;i<4;i++) sH[r*132 + lane+32*i] = fmaf(alpha, v[i]*rs, beta);
    }

    const int tx = threadIdx.x & 15, ty = threadIdx.x >> 4;  // rows ty*4.., cols tx*8..
    float oacc[4][8];
#pragma unroll
    for (int i=0;i<4;i++){
#pragma unroll
        for (int j=0;j<8;j++) oacc[i][j] = 0.f;
    }

    for (int nt=0;nt<4;nt++){
        float a1[4][8];
#pragma unroll
        for (int i=0;i<4;i++){
#pragma unroll
            for (int j=0;j<8;j++) a1[i][j] = 0.f;
        }
        // GEMM1: h(64x128) @ W1[:, nt*128 : nt*128+128]
        for (int kc=0;kc<4;kc++){
            __syncthreads();
            for (int i=threadIdx.x;i<1024;i+=256){
                int k = i>>5, n4 = i&31;
                *(float4*)(sW + k*132 + (n4<<2)) =
                    *(const float4*)(W1 + (size_t)((kc<<5)+k)*512 + nt*128 + (n4<<2));
            }
            __syncthreads();
#pragma unroll
            for (int kk=0;kk<32;kk++){
                float a4[4];
#pragma unroll
                for (int i=0;i<4;i++) a4[i] = sH[(ty*4+i)*132 + (kc<<5)+kk];
                float4 b0 = *(const float4*)(sW + kk*132 + tx*8);
                float4 b1v = *(const float4*)(sW + kk*132 + tx*8 + 4);
                float b8[8] = {b0.x,b0.y,b0.z,b0.w,b1v.x,b1v.y,b1v.z,b1v.w};
#pragma unroll
                for (int i=0;i<4;i++){
#pragma unroll
                    for (int j=0;j<8;j++) a1[i][j] = fmaf(a4[i], b8[j], a1[i][j]);
                }
            }
        }
        // gelu -> sM
#pragma unroll
        for (int i=0;i<4;i++){
            int row = ty*4+i;
#pragma unroll
            for (int j=0;j<8;j++){
                int col = tx*8+j;
                sM[row*132+col] = gelu_tanh(a1[i][j] + b1[nt*128+col]);
            }
        }
        // GEMM2: oacc += m_tile(64x128) @ W2[nt*128 : nt*128+128, :]
        for (int kc=0;kc<4;kc++){
            __syncthreads();
            for (int i=threadIdx.x;i<1024;i+=256){
                int k = i>>5, n4 = i&31;
                *(float4*)(sW + k*132 + (n4<<2)) =
                    *(const float4*)(W2 + (size_t)(nt*128 + (kc<<5)+k)*128 + (n4<<2));
            }
            __syncthreads();
#pragma unroll
            for (int kk=0;kk<32;kk++){
                float a4[4];
#pragma unroll
                for (int i=0;i<4;i++) a4[i] = sM[(ty*4+i)*132 + (kc<<5)+kk];
                float4 b0 = *(const float4*)(sW + kk*132 + tx*8);
                float4 b1v = *(const float4*)(sW + kk*132 + tx*8 + 4);
                float b8[8] = {b0.x,b0.y,b0.z,b0.w,b1v.x,b1v.y,b1v.z,b1v.w};
#pragma unroll
                for (int i=0;i<4;i++){
#pragma unroll
                    for (int j=0;j<8;j++) oacc[i][j] = fmaf(a4[i], b8[j], oacc[i][j]);
                }
            }
        }
    }
    // out = x2 + g2 * (m + b2)
#pragma unroll
    for (int i=0;i<4;i++){
        int row = ty*4+i;
#pragma unroll
        for (int j=0;j<8;j++){
            int col = tx*8+j;
            size_t o = (size_t)(t0+row)*128 + col;
            float xv = xo[o];
            xo[o] = fmaf(g2, oacc[i][j] + b2[col], xv);
        }
    }
}

// ---------------- launch ---------------------------------------------------
extern "C" void kernel_launch(void* const* d_in, const int* in_sizes, int n_in,
                              void* d_out, int out_size)
{
    (void)in_sizes; (void)n_in; (void)out_size;
    const float* F[28];
    for (int i=0;i<28;i++) F[i] = (const float*)d_in[i];
    float* out = (float*)d_out;

    cudaFuncSetAttribute(k1_gates, cudaFuncAttributeMaxDynamicSharedMemorySize, 152064);
    cudaFuncSetAttribute(k4_mlp,   cudaFuncAttributeMaxDynamicSharedMemorySize, 84480);

    // conditioning scalars
    k_affine<<<1,256>>>(F[1], F[2],F[3],F[4],F[5],F[6],F[7],
                              F[18],F[19],F[20],F[21],F[22],F[23]);
    // branch 1 gates
    k1_gates<<<512,256,152064>>>(F[0], F[8], F[9], F[10],
                                 F[11], F[12], F[13], F[14], F[15]);
    // bidirectional scan
    dim3 g2(BSZ, NC);
    k2_reduce<<<g2,128>>>();
    k2_carry<<<BSZ,128>>>();
    k2_apply<<<g2,128>>>();
    // rnn out projection + gated residual -> d_out holds x2
    k3_out<<<512,256>>>(F[0], F[16], F[17], out);
    // branch 2 MLP, in place on d_out
    k4_mlp<<<1024,256,84480>>>(out, F[24], F[25], F[26], F[27]);
}

// round 4
// speedup vs baseline: 1.7860x; 1.7860x over previous
#include <cuda_runtime.h>
#include <cuda_bf16.h>
#include <math.h>
#include <stdint.h>

#define BSZ 8
#define LQ 8192
#define NTOK (BSZ*LQ)
#define NC 64
#define CL 128
#define TP 136                      // padded tile row (bf16 elems)
#define TILE_B (128*TP*2)           // tile bytes = 34816

// ---------------- scratch (device globals; no allocations allowed) ----------
__device__ float g_at[(size_t)NTOK*128];
__device__ float g_bt[(size_t)NTOK*128];
__device__ float g_hf[(size_t)NTOK*128];
__device__ float g_hb[(size_t)NTOK*128];
__device__ float g_cfA[BSZ*NC*128], g_cfB[BSZ*NC*128];
__device__ float g_cbA[BSZ*NC*128], g_cbB[BSZ*NC*128];
__device__ float g_carF[BSZ*NC*128], g_carB[BSZ*NC*128];
__device__ float g_scal[BSZ*6];

// ---------------- helpers ---------------------------------------------------
__device__ __forceinline__ float warp_allred(float v){
#pragma unroll
    for (int o=16;o>0;o>>=1) v += __shfl_xor_sync(0xffffffffu, v, o);
    return v;
}
__device__ __forceinline__ float sigmoidf_(float z){
    return __fdividef(1.f, 1.f + __expf(-z));
}
__device__ __forceinline__ float gelu_tanh(float v){
    float t;
    asm("tanh.approx.f32 %0, %1;" : "=f"(t) : "f"(0.7978845608028654f * fmaf(0.044715f*v, v*v, v)));
    return 0.5f*v*(1.f+t);
}
__device__ __forceinline__ void split_store(__nv_bfloat16* hi, __nv_bfloat16* lo,
                                            int off, float v){
    __nv_bfloat16 h = __float2bfloat16(v);
    hi[off] = h;
    lo[off] = __float2bfloat16(v - __bfloat162float(h));
}

// mma.sync m16n8k16 bf16 -> f32 (portable sm_80+ PTX; runs on tensor pipe)
__device__ __forceinline__ void mma16816(float c[4], uint32_t a0, uint32_t a1,
                                         uint32_t a2, uint32_t a3,
                                         uint32_t b0, uint32_t b1){
    asm volatile(
        "mma.sync.aligned.m16n8k16.row.col.f32.bf16.bf16.f32 "
        "{%0,%1,%2,%3},{%4,%5,%6,%7},{%8,%9},{%0,%1,%2,%3};"
        : "+f"(c[0]),"+f"(c[1]),"+f"(c[2]),"+f"(c[3])
        : "r"(a0),"r"(a1),"r"(a2),"r"(a3),"r"(b0),"r"(b1));
}

// C[128x128] += A[128x128] * B^T (B stored transposed [n][k]), bf16x3 passes.
// Warp tile: 32 rows x 64 cols -> acc[2][8][4].
__device__ __forceinline__ void gemm_x3(
    const __nv_bfloat16* __restrict__ sAhi, const __nv_bfloat16* __restrict__ sAlo,
    const __nv_bfloat16* __restrict__ sBhi, const __nv_bfloat16* __restrict__ sBlo,
    float acc[2][8][4], int mrow0, int ncol0, int lane)
{
    const int group = lane>>2, tig = lane&3;
#pragma unroll 1
    for (int p=0;p<3;p++){
        const __nv_bfloat16* A = (p==2) ? sAlo : sAhi;
        const __nv_bfloat16* B = (p==1) ? sBlo : sBhi;
#pragma unroll 1
        for (int kt=0;kt<8;kt++){
            const int k0 = kt*16;
            uint32_t af[2][4];
#pragma unroll
            for (int mt=0;mt<2;mt++){
                const __nv_bfloat16* ar = A + (mrow0+16*mt+group)*TP + k0 + 2*tig;
                af[mt][0] = *(const uint32_t*)(ar);
                af[mt][1] = *(const uint32_t*)(ar + 8*TP);
                af[mt][2] = *(const uint32_t*)(ar + 8);
                af[mt][3] = *(const uint32_t*)(ar + 8*TP + 8);
            }
#pragma unroll
            for (int nt=0;nt<8;nt++){
                const __nv_bfloat16* br = B + (ncol0+8*nt+group)*TP + k0 + 2*tig;
                uint32_t b0 = *(const uint32_t*)(br);
                uint32_t b1 = *(const uint32_t*)(br + 8);
                mma16816(acc[0][nt], af[0][0],af[0][1],af[0][2],af[0][3], b0,b1);
                mma16816(acc[1][nt], af[1][0],af[1][1],af[1][2],af[1][3], b0,b1);
            }
        }
    }
}

__device__ __forceinline__ void zero_acc(float acc[2][8][4]){
#pragma unroll
    for (int m=0;m<2;m++)
#pragma unroll
        for (int n=0;n<8;n++)
#pragma unroll
            for (int q=0;q<4;q++) acc[m][n][q] = 0.f;
}

// W[k][col0+n] (row stride ldw) -> transposed hi/lo tiles [n][k]
__device__ __forceinline__ void load_w_t(const float* __restrict__ W, int ldw, int col0,
                                         __nv_bfloat16* sBhi, __nv_bfloat16* sBlo){
    for (int idx = threadIdx.x; idx < 16384; idx += 256){
        int k = idx >> 7, n = idx & 127;
        split_store(sBhi, sBlo, n*TP + k, W[(size_t)k*ldw + col0 + n]);
    }
}
// row-major fp32 [128][128] -> hi/lo tiles [r][c]
__device__ __forceinline__ void load_a_g(const float* __restrict__ src,
                                         __nv_bfloat16* sAhi, __nv_bfloat16* sAlo){
    for (int idx = threadIdx.x; idx < 16384; idx += 256){
        split_store(sAhi, sAlo, (idx>>7)*TP + (idx&127), src[idx]);
    }
}

// ---------------- K0: conditioning scalars ----------------------------------
__global__ __launch_bounds__(256) void k_affine(
    const float* __restrict__ c,
    const float* __restrict__ sw1, const float* __restrict__ sb1,
    const float* __restrict__ bw1, const float* __restrict__ bb1,
    const float* __restrict__ gw1, const float* __restrict__ gb1,
    const float* __restrict__ sw2, const float* __restrict__ sb2,
    const float* __restrict__ bw2, const float* __restrict__ bb2,
    const float* __restrict__ gw2, const float* __restrict__ gb2)
{
    int warp = threadIdx.x>>5, lane = threadIdx.x&31;
    if (warp >= BSZ) return;
    const float* ws[6] = {sw1,bw1,gw1,sw2,bw2,gw2};
    const float* bs[6] = {sb1,bb1,gb1,sb2,bb2,gb2};
    for (int j=0;j<6;j++){
        float s = 0.f;
        for (int i=lane;i<128;i+=32) s += c[warp*128+i]*ws[j][i];
#pragma unroll
        for (int o=16;o>0;o>>=1) s += __shfl_down_sync(0xffffffffu, s, o);
        if (lane==0) g_scal[warp*6+j] = s + bs[j][0];
    }
}

// ---------------- K1: LN chain + u/gr/gi GEMMs + at,bt ----------------------
__global__ __launch_bounds__(256) void k1_gates(
    const float* __restrict__ x,
    const float* __restrict__ Win, const float* __restrict__ bin,
    const float* __restrict__ pos,
    const float* __restrict__ Wi,  const float* __restrict__ bi,
    const float* __restrict__ Wr,  const float* __restrict__ br,
    const float* __restrict__ ra)
{
    extern __shared__ __align__(16) char smraw[];
    __nv_bfloat16* sAhi = (__nv_bfloat16*)smraw;
    __nv_bfloat16* sAlo = sAhi + 128*TP;
    __nv_bfloat16* sBhi = sAlo + 128*TP;
    __nv_bfloat16* sBlo = sBhi + 128*TP;
    float* sC  = (float*)(smraw + 4*TILE_B);        // u staging [128][132]
    float* sLa = (float*)(smraw + 4*TILE_B + 128*132*4);
    const int tid = threadIdx.x, wid = tid>>5, lane = tid&31;
    const int t0 = blockIdx.x*128, b = t0/LQ, l0 = t0%LQ;
    const float alpha = 1.f + g_scal[b*6+0];
    const float beta  = g_scal[b*6+1];
    const int mrow0 = (wid>>1)*32, ncol0 = (wid&1)*64;
    const int group = lane>>2, tig = lane&3;

    if (tid < 128) sLa[tid] = 8.f*logf(ra[tid]);

    // LN(x)->h->LN(h) = v -> hi/lo A tiles (warp per row)
    for (int r = wid; r < 128; r += 8){
        const float* xr = x + (size_t)(t0+r)*128;
        float v[4];
#pragma unroll
        for (int i=0;i<4;i++) v[i] = xr[lane+32*i];
        float m = warp_allred(v[0]+v[1]+v[2]+v[3]) * (1.f/128.f);
        float sq = 0.f;
#pragma unroll
        for (int i=0;i<4;i++){ v[i] -= m; sq += v[i]*v[i]; }
        float rs = rsqrtf(warp_allred(sq)*(1.f/128.f) + 1e-6f);
#pragma unroll
        for (int i=0;i<4;i++) v[i] = fmaf(alpha, v[i]*rs, beta);
        float m2 = warp_allred(v[0]+v[1]+v[2]+v[3]) * (1.f/128.f);
        float sq2 = 0.f;
#pragma unroll
        for (int i=0;i<4;i++){ v[i] -= m2; sq2 += v[i]*v[i]; }
        float rs2 = rsqrtf(warp_allred(sq2)*(1.f/128.f) + 1e-6f);
#pragma unroll
        for (int i=0;i<4;i++) split_store(sAhi, sAlo, r*TP + lane+32*i, v[i]*rs2);
    }
    load_w_t(Win, 128, 0, sBhi, sBlo);
    __syncthreads();

    float acc[2][8][4];
    // GEMM1: u = v @ Win
    zero_acc(acc);
    gemm_x3(sAhi, sAlo, sBhi, sBlo, acc, mrow0, ncol0, lane);
    __syncthreads();

    // epilogue 1: u = acc + bin + pos -> sC and sA tiles
#pragma unroll
    for (int mt=0;mt<2;mt++){
        int r0 = mrow0+16*mt+group, r1 = r0+8;
#pragma unroll
        for (int nt=0;nt<8;nt++){
            int col = ncol0+8*nt+2*tig;
            float bc0 = __ldg(bin+col), bc1 = __ldg(bin+col+1);
            float2 p0 = *(const float2*)(pos + (size_t)(l0+r0)*128 + col);
            float2 p1 = *(const float2*)(pos + (size_t)(l0+r1)*128 + col);
            float u00 = acc[mt][nt][0] + bc0 + p0.x;
            float u01 = acc[mt][nt][1] + bc1 + p0.y;
            float u10 = acc[mt][nt][2] + bc0 + p1.x;
            float u11 = acc[mt][nt][3] + bc1 + p1.y;
            *(float2*)(sC + r0*132 + col) = make_float2(u00,u01);
            *(float2*)(sC + r1*132 + col) = make_float2(u10,u11);
            split_store(sAhi,sAlo, r0*TP+col,   u00);
            split_store(sAhi,sAlo, r0*TP+col+1, u01);
            split_store(sAhi,sAlo, r1*TP+col,   u10);
            split_store(sAhi,sAlo, r1*TP+col+1, u11);
        }
    }
    load_w_t(Wr, 128, 0, sBhi, sBlo);
    __syncthreads();

    // GEMM2: gr = sigmoid(u @ Wr + br); at = exp(8*gr*log a)
    zero_acc(acc);
    gemm_x3(sAhi, sAlo, sBhi, sBlo, acc, mrow0, ncol0, lane);
    __syncthreads();
#pragma unroll
    for (int mt=0;mt<2;mt++){
        int r0 = mrow0+16*mt+group, r1 = r0+8;
#pragma unroll
        for (int nt=0;nt<8;nt++){
            int col = ncol0+8*nt+2*tig;
            float bc0 = __ldg(br+col), bc1 = __ldg(br+col+1);
            float la0 = sLa[col], la1 = sLa[col+1];
            float a00 = __expf(sigmoidf_(acc[mt][nt][0]+bc0)*la0);
            float a01 = __expf(sigmoidf_(acc[mt][nt][1]+bc1)*la1);
            float a10 = __expf(sigmoidf_(acc[mt][nt][2]+bc0)*la0);
            float a11 = __expf(sigmoidf_(acc[mt][nt][3]+bc1)*la1);
            *(float2*)(g_at + (size_t)(t0+r0)*128 + col) = make_float2(a00,a01);
            *(float2*)(g_at + (size_t)(t0+r1)*128 + col) = make_float2(a10,a11);
            float2 u0 = *(const float2*)(sC + r0*132 + col);
            float2 u1 = *(const float2*)(sC + r1*132 + col);
            u0.x *= sqrtf(fmaxf(1.f-a00*a00,0.f));
            u0.y *= sqrtf(fmaxf(1.f-a01*a01,0.f));
            u1.x *= sqrtf(fmaxf(1.f-a10*a10,0.f));
            u1.y *= sqrtf(fmaxf(1.f-a11*a11,0.f));
            *(float2*)(sC + r0*132 + col) = u0;
            *(float2*)(sC + r1*132 + col) = u1;
        }
    }
    load_w_t(Wi, 128, 0, sBhi, sBlo);
    __syncthreads();

    // GEMM3: gi = sigmoid(u @ Wi + bi); bt = gi * sqrt(1-at^2)*u
    zero_acc(acc);
    gemm_x3(sAhi, sAlo, sBhi, sBlo, acc, mrow0, ncol0, lane);
#pragma unroll
    for (int mt=0;mt<2;mt++){
        int r0 = mrow0+16*mt+group, r1 = r0+8;
#pragma unroll
        for (int nt=0;nt<8;nt++){
            int col = ncol0+8*nt+2*tig;
            float bc0 = __ldg(bi+col), bc1 = __ldg(bi+col+1);
            float2 u0 = *(const float2*)(sC + r0*132 + col);
            float2 u1 = *(const float2*)(sC + r1*132 + col);
            float b00 = sigmoidf_(acc[mt][nt][0]+bc0)*u0.x;
            float b01 = sigmoidf_(acc[mt][nt][1]+bc1)*u0.y;
            float b10 = sigmoidf_(acc[mt][nt][2]+bc0)*u1.x;
            float b11 = sigmoidf_(acc[mt][nt][3]+bc1)*u1.y;
            *(float2*)(g_bt + (size_t)(t0+r0)*128 + col) = make_float2(b00,b01);
            *(float2*)(g_bt + (size_t)(t0+r1)*128 + col) = make_float2(b10,b11);
        }
    }
}

// ---------------- K2: chunked bidirectional scan ----------------------------
__global__ __launch_bounds__(128) void k2_reduce(){
    int b = blockIdx.x, c = blockIdx.y, d = threadIdx.x;
    size_t base = ((size_t)b*LQ + (size_t)c*CL)*128 + d;
    const float* A = g_at + base;
    const float* B = g_bt + base;
    float Af=1.f, Bf=0.f;
#pragma unroll 4
    for (int i=0;i<CL;i++){ float a=A[(size_t)i*128], bb=B[(size_t)i*128]; Bf=fmaf(a,Bf,bb); Af*=a; }
    int ci = (b*NC+c)*128+d;
    g_cfA[ci]=Af; g_cfB[ci]=Bf;
    float Ab=1.f, Bb=0.f;
#pragma unroll 4
    for (int i=CL-1;i>=0;i--){ float a=A[(size_t)i*128], bb=B[(size_t)i*128]; Bb=fmaf(a,Bb,bb); Ab*=a; }
    g_cbA[ci]=Ab; g_cbB[ci]=Bb;
}

__global__ __launch_bounds__(128) void k2_carry(){
    extern __shared__ __align__(16) char smraw[];
    float* sA = (float*)smraw; float* sB = sA + 8192;
    int b = blockIdx.x; bool fwd = (blockIdx.y == 0);
    const float* A = fwd ? g_cfA : g_cbA;
    const float* B = fwd ? g_cfB : g_cbB;
    float* car = fwd ? g_carF : g_carB;
    for (int i=threadIdx.x;i<8192;i+=128){ sA[i]=A[b*8192+i]; sB[i]=B[b*8192+i]; }
    __syncthreads();
    int d = threadIdx.x;
    float h = 0.f;
    if (fwd){
        for (int c=0;c<NC;c++){
            car[(b*NC+c)*128+d] = h;
            h = fmaf(sA[c*128+d], h, sB[c*128+d]);
        }
    } else {
        for (int c=NC-1;c>=0;c--){
            car[(b*NC+c)*128+d] = h;
            h = fmaf(sA[c*128+d], h, sB[c*128+d]);
        }
    }
}

__global__ __launch_bounds__(128) void k2_apply(){
    int b = blockIdx.x, c = blockIdx.y, d = threadIdx.x;
    size_t base = ((size_t)b*LQ + (size_t)c*CL)*128 + d;
    int ci = (b*NC+c)*128+d;
    float h = g_carF[ci];
#pragma unroll 4
    for (int i=0;i<CL;i++){
        size_t o = base + (size_t)i*128;
        h = fmaf(g_at[o], h, g_bt[o]); g_hf[o] = h;
    }
    float h2 = g_carB[ci];
#pragma unroll 4
    for (int i=CL-1;i>=0;i--){
        size_t o = base + (size_t)i*128;
        h2 = fmaf(g_at[o], h2, g_bt[o]); g_hb[o] = h2;
    }
}

// ---------------- K3: r = [hf|hb]@Wo + bo; out = x + g1*r -------------------
__global__ __launch_bounds__(256) void k3_out(
    const float* __restrict__ x, const float* __restrict__ Wo,
    const float* __restrict__ bo, float* __restrict__ out)
{
    extern __shared__ __align__(16) char smraw[];
    __nv_bfloat16* sAhi = (__nv_bfloat16*)smraw;
    __nv_bfloat16* sAlo = sAhi + 128*TP;
    __nv_bfloat16* sBhi = sAlo + 128*TP;
    __nv_bfloat16* sBlo = sBhi + 128*TP;
    const int tid = threadIdx.x, wid = tid>>5, lane = tid&31;
    const int t0 = blockIdx.x*128, b = t0/LQ;
    const float g1 = g_scal[b*6+2];
    const int mrow0 = (wid>>1)*32, ncol0 = (wid&1)*64;
    const int group = lane>>2, tig = lane&3;

    load_a_g(g_hf + (size_t)t0*128, sAhi, sAlo);
    load_w_t(Wo, 128, 0, sBhi, sBlo);
    __syncthreads();
    float acc[2][8][4];
    zero_acc(acc);
    gemm_x3(sAhi, sAlo, sBhi, sBlo, acc, mrow0, ncol0, lane);
    __syncthreads();
    load_a_g(g_hb + (size_t)t0*128, sAhi, sAlo);
    load_w_t(Wo + 128*128, 128, 0, sBhi, sBlo);
    __syncthreads();
    gemm_x3(sAhi, sAlo, sBhi, sBlo, acc, mrow0, ncol0, lane);

#pragma unroll
    for (int mt=0;mt<2;mt++){
        int r0 = mrow0+16*mt+group, r1 = r0+8;
#pragma unroll
        for (int nt=0;nt<8;nt++){
            int col = ncol0+8*nt+2*tig;
            float bc0 = __ldg(bo+col), bc1 = __ldg(bo+col+1);
            float2 x0 = *(const float2*)(x + (size_t)(t0+r0)*128 + col);
            float2 x1 = *(const float2*)(x + (size_t)(t0+r1)*128 + col);
            float o00 = fmaf(g1, acc[mt][nt][0]+bc0, x0.x);
            float o01 = fmaf(g1, acc[mt][nt][1]+bc1, x0.y);
            float o10 = fmaf(g1, acc[mt][nt][2]+bc0, x1.x);
            float o11 = fmaf(g1, acc[mt][nt][3]+bc1, x1.y);
            *(float2*)(out + (size_t)(t0+r0)*128 + col) = make_float2(o00,o01);
            *(float2*)(out + (size_t)(t0+r1)*128 + col) = make_float2(o10,o11);
        }
    }
}

// ---------------- K4: conditioned LN + gelu MLP + gated residual ------------
__global__ __launch_bounds__(256) void k4_mlp(
    float* __restrict__ xo,
    const float* __restrict__ W1, const float* __restrict__ b1,
    const float* __restrict__ W2, const float* __restrict__ b2)
{
    extern __shared__ __align__(16) char smraw[];
    __nv_bfloat16* sAhi = (__nv_bfloat16*)smraw;
    __nv_bfloat16* sAlo = sAhi + 128*TP;
    __nv_bfloat16* sBhi = sAlo + 128*TP;
    __nv_bfloat16* sBlo = sBhi + 128*TP;
    __nv_bfloat16* sMhi = sBlo + 128*TP;
    __nv_bfloat16* sMlo = sMhi + 128*TP;
    const int tid = threadIdx.x, wid = tid>>5, lane = tid&31;
    const int t0 = blockIdx.x*128, b = t0/LQ;
    const float alpha = 1.f + g_scal[b*6+3];
    const float beta  = g_scal[b*6+4];
    const float g2    = g_scal[b*6+5];
    const int mrow0 = (wid>>1)*32, ncol0 = (wid&1)*64;
    const int group = lane>>2, tig = lane&3;

    // conditioned LN(x2) -> sA tiles
    for (int r = wid; r < 128; r += 8){
        const float* xr = xo + (size_t)(t0+r)*128;
        float v[4];
#pragma unroll
        for (int i=0;i<4;i++) v[i] = xr[lane+32*i];
        float m = warp_allred(v[0]+v[1]+v[2]+v[3]) * (1.f/128.f);
        float sq = 0.f;
#pragma unroll
        for (int i=0;i<4;i++){ v[i] -= m; sq += v[i]*v[i]; }
        float rs = rsqrtf(warp_allred(sq)*(1.f/128.f) + 1e-6f);
#pragma unroll
        for (int i=0;i<4;i++) split_store(sAhi, sAlo, r*TP + lane+32*i, fmaf(alpha, v[i]*rs, beta));
    }

    float acc[2][8][4], oacc[2][8][4];
    zero_acc(oacc);
#pragma unroll 1
    for (int nt4=0; nt4<4; nt4++){
        __syncthreads();
        load_w_t(W1, 512, nt4*128, sBhi, sBlo);
        __syncthreads();
        zero_acc(acc);
        gemm_x3(sAhi, sAlo, sBhi, sBlo, acc, mrow0, ncol0, lane);
        __syncthreads();
        // gelu -> sM tiles
#pragma unroll
        for (int mt=0;mt<2;mt++){
            int r0 = mrow0+16*mt+group, r1 = r0+8;
#pragma unroll
            for (int nt=0;nt<8;nt++){
                int col = ncol0+8*nt+2*tig;
                float bc0 = __ldg(b1+nt4*128+col), bc1 = __ldg(b1+nt4*128+col+1);
                split_store(sMhi,sMlo, r0*TP+col,   gelu_tanh(acc[mt][nt][0]+bc0));
                split_store(sMhi,sMlo, r0*TP+col+1, gelu_tanh(acc[mt][nt][1]+bc1));
                split_store(sMhi,sMlo, r1*TP+col,   gelu_tanh(acc[mt][nt][2]+bc0));
                split_store(sMhi,sMlo, r1*TP+col+1, gelu_tanh(acc[mt][nt][3]+bc1));
            }
        }
        load_w_t(W2 + (size_t)(nt4*128)*128, 128, 0, sBhi, sBlo);
        __syncthreads();
        gemm_x3(sMhi, sMlo, sBhi, sBlo, oacc, mrow0, ncol0, lane);
    }

#pragma unroll
    for (int mt=0;mt<2;mt++){
        int r0 = mrow0+16*mt+group, r1 = r0+8;
#pragma unroll
        for (int nt=0;nt<8;nt++){
            int col = ncol0+8*nt+2*tig;
            float bc0 = __ldg(b2+col), bc1 = __ldg(b2+col+1);
            float2 x0 = *(const float2*)(xo + (size_t)(t0+r0)*128 + col);
            float2 x1 = *(const float2*)(xo + (size_t)(t0+r1)*128 + col);
            float o00 = fmaf(g2, oacc[mt][nt][0]+bc0, x0.x);
            float o01 = fmaf(g2, oacc[mt][nt][1]+bc1, x0.y);
            float o10 = fmaf(g2, oacc[mt][nt][2]+bc0, x1.x);
            float o11 = fmaf(g2, oacc[mt][nt][3]+bc1, x1.y);
            *(float2*)(xo + (size_t)(t0+r0)*128 + col) = make_float2(o00,o01);
            *(float2*)(xo + (size_t)(t0+r1)*128 + col) = make_float2(o10,o11);
        }
    }
}

// ---------------- launch ----------------------------------------------------
extern "C" void kernel_launch(void* const* d_in, const int* in_sizes, int n_in,
                              void* d_out, int out_size)
{
    (void)in_sizes; (void)n_in; (void)out_size;
    const float* F[28];
    for (int i=0;i<28;i++) F[i] = (const float*)d_in[i];
    float* out = (float*)d_out;

    const int K1_SMEM = 4*TILE_B + 128*132*4 + 512;  // 139264+67584+512 = 207360
    const int K3_SMEM = 4*TILE_B;                    // 139264
    const int K4_SMEM = 6*TILE_B;                    // 208896
    cudaFuncSetAttribute(k1_gates, cudaFuncAttributeMaxDynamicSharedMemorySize, K1_SMEM);
    cudaFuncSetAttribute(k3_out,   cudaFuncAttributeMaxDynamicSharedMemorySize, K3_SMEM);
    cudaFuncSetAttribute(k4_mlp,   cudaFuncAttributeMaxDynamicSharedMemorySize, K4_SMEM);
    cudaFuncSetAttribute(k2_carry, cudaFuncAttributeMaxDynamicSharedMemorySize, 65536);

    k_affine<<<1,256>>>(F[1], F[2],F[3],F[4],F[5],F[6],F[7],
                              F[18],F[19],F[20],F[21],F[22],F[23]);
    k1_gates<<<512,256,K1_SMEM>>>(F[0], F[8], F[9], F[10],
                                  F[11], F[12], F[13], F[14], F[15]);
    dim3 gr2(BSZ, NC);
    k2_reduce<<<gr2,128>>>();
    k2_carry<<<dim3(BSZ,2),128,65536>>>();
    k2_apply<<<gr2,128>>>();
    k3_out<<<512,256,K3_SMEM>>>(F[0], F[16], F[17], out);
    k4_mlp<<<512,256,K4_SMEM>>>(out, F[24], F[25], F[26], F[27]);
}